// round 13
// baseline (speedup 1.0000x reference)
#include <cuda_runtime.h>
#include <cstdint>

#define C_DIM 1024
#define B_DIM 4
#define T_DIM 2048
#define H_DIM 16
#define HD    64
#define M_TOT (B_DIM * T_DIM)   // 8192
#define N_TOT (3 * C_DIM)       // 3072

// Q/K in [B,H,T,D]; V TRANSPOSED in [B,H,D,T] with time-index permuted
// within each 8-block (PV-mma layout). All tf32-rounded fp32 bits.
__device__ float g_q[(size_t)M_TOT * C_DIM];
__device__ float g_k[(size_t)M_TOT * C_DIM];
__device__ float g_v[(size_t)M_TOT * C_DIM];
// tf32-rounded copies of inputs
__device__ float g_xt[(size_t)M_TOT * C_DIM];
__device__ float g_wt[(size_t)N_TOT * C_DIM];

__device__ __forceinline__ uint32_t f2tf(float f) {
    uint32_t u;
    asm("cvt.rna.tf32.f32 %0, %1;" : "=r"(u) : "f"(f));
    return u;
}

__device__ __forceinline__ float ex2(float x) {
    float y;
    asm("ex2.approx.f32 %0, %1;" : "=f"(y) : "f"(x));
    return y;
}

__device__ __forceinline__ void mma_tf32(float c[4], const uint32_t a[4],
                                         uint32_t b0, uint32_t b1) {
    asm volatile(
        "mma.sync.aligned.m16n8k8.row.col.f32.tf32.tf32.f32 "
        "{%0,%1,%2,%3}, {%4,%5,%6,%7}, {%8,%9}, {%0,%1,%2,%3};"
        : "+f"(c[0]), "+f"(c[1]), "+f"(c[2]), "+f"(c[3])
        : "r"(a[0]), "r"(a[1]), "r"(a[2]), "r"(a[3]), "r"(b0), "r"(b1));
}

__device__ __forceinline__ void ldsm4(uint32_t& d0, uint32_t& d1,
                                      uint32_t& d2, uint32_t& d3,
                                      uint32_t addr) {
    asm volatile("ldmatrix.sync.aligned.m8n8.x4.shared.b16 {%0,%1,%2,%3}, [%4];"
                 : "=r"(d0), "=r"(d1), "=r"(d2), "=r"(d3) : "r"(addr));
}

__device__ __forceinline__ uint32_t smem_u32(const void* p) {
    uint32_t a;
    asm("{ .reg .u64 t; cvta.to.shared.u64 t, %1; cvt.u32.u64 %0, t; }"
        : "=r"(a) : "l"(p));
    return a;
}

__device__ __forceinline__ void cp16(uint32_t dst, const void* src) {
    asm volatile("cp.async.cg.shared.global [%0], [%1], 16;"
                 :: "r"(dst), "l"(src));
}
#define CP_COMMIT() asm volatile("cp.async.commit_group;" ::: "memory")
#define CP_WAIT0()  asm volatile("cp.async.wait_group 0;" ::: "memory")
#define CP_WAIT2()  asm volatile("cp.async.wait_group 2;" ::: "memory")

// ---------------------------------------------------------------------------
// Prepass: tf32-round (rna) x and W into scratch copies.
// ---------------------------------------------------------------------------
__global__ __launch_bounds__(256) void cvt_pre(
    const float* __restrict__ x, const float* __restrict__ W)
{
    const size_t nx = (size_t)M_TOT * C_DIM / 4;
    const size_t nw = (size_t)N_TOT * C_DIM / 4;
    size_t i = (size_t)blockIdx.x * blockDim.x + threadIdx.x;
    if (i < nx) {
        float4 v = ((const float4*)x)[i];
        uint4 u = { f2tf(v.x), f2tf(v.y), f2tf(v.z), f2tf(v.w) };
        ((uint4*)g_xt)[i] = u;
    } else if (i < nx + nw) {
        float4 v = ((const float4*)W)[i - nx];
        uint4 u = { f2tf(v.x), f2tf(v.y), f2tf(v.z), f2tf(v.w) };
        ((uint4*)g_wt)[i - nx] = u;
    }
}

// ---------------------------------------------------------------------------
// QKV GEMM: CTA 128x128, k16, 4 warps (2M x 2N), WARP TILE 64x64.
// 4-stage cp.async ring, ONE sync per k-tile, ldmatrix fragments.
// Q/K scattered (tf32-rounded) to [B,H,T,D]; V transposed to [B,H,D,T]
// with time index PERMUTED within each 8-block: t' = ((t&1)<<2)|((t&7)>>1).
// ---------------------------------------------------------------------------
#define GPAD 20
#define GSTAGE_U32 (128 * GPAD)
#define GEMM_SMEM_BYTES (8 * GSTAGE_U32 * 4)   // (A+B) x 4 stages = 81920 B

__global__ __launch_bounds__(128, 2) void qkv_gemm_tf32(
    const float* __restrict__ b)
{
    extern __shared__ uint32_t gsm[];
    uint32_t* Abuf = gsm;                     // [4][128][GPAD]
    uint32_t* Bbuf = gsm + 4 * GSTAGE_U32;    // [4][128][GPAD]

    const int tid  = threadIdx.x;
    const int lane = tid & 31;
    const int warp = tid >> 5;
    const int wm = warp >> 1;                 // 0..1
    const int wn = warp & 1;                  // 0..1
    const int m0 = blockIdx.y * 128;
    const int n0 = blockIdx.x * 128;

    const uint32_t aBase = smem_u32(Abuf);
    const uint32_t bBase = smem_u32(Bbuf);

    const uint32_t offA = ((((lane & 7) + ((lane >> 3) & 1) * 8) * GPAD)
                           + (lane >> 4) * 4) * 4;
    const uint32_t offBP = ((((lane & 7) + (lane >> 4) * 8) * GPAD)
                            + ((lane >> 3) & 1) * 4) * 4;

    // staging: thread = one row (128 rows), 16 floats = 4 cp16 each for A and B
    const float* ap = g_xt + (size_t)(m0 + tid) * C_DIM;
    const float* bp = g_wt + (size_t)(n0 + tid) * C_DIM;
    const uint32_t aDst = aBase + (tid * GPAD) * 4;
    const uint32_t bDst = bBase + (tid * GPAD) * 4;

    float acc[4][8][4] = {};

    #pragma unroll
    for (int s = 0; s < 3; s++) {
        const uint32_t so = (uint32_t)s * (GSTAGE_U32 * 4);
        #pragma unroll
        for (int i = 0; i < 4; i++) {
            cp16(aDst + so + i * 16, ap + s * 16 + i * 4);
            cp16(bDst + so + i * 16, bp + s * 16 + i * 4);
        }
        CP_COMMIT();
    }

    #pragma unroll 1
    for (int kt = 0; kt < 64; kt++) {
        CP_WAIT2();
        __syncthreads();

        if (kt + 3 < 64) {
            const int kn = kt + 3;
            const uint32_t so = (uint32_t)(kn & 3) * (GSTAGE_U32 * 4);
            #pragma unroll
            for (int i = 0; i < 4; i++) {
                cp16(aDst + so + i * 16, ap + kn * 16 + i * 4);
                cp16(bDst + so + i * 16, bp + kn * 16 + i * 4);
            }
        }
        CP_COMMIT();

        const uint32_t aS = aBase + (uint32_t)(kt & 3) * (GSTAGE_U32 * 4);
        const uint32_t bS = bBase + (uint32_t)(kt & 3) * (GSTAGE_U32 * 4);

        #pragma unroll
        for (int ks = 0; ks < 16; ks += 8) {
            uint32_t af[4][4];
            #pragma unroll
            for (int mt = 0; mt < 4; mt++) {
                ldsm4(af[mt][0], af[mt][1], af[mt][2], af[mt][3],
                      aS + ((wm * 64 + mt * 16) * GPAD + ks) * 4 + offA);
            }
            uint32_t bf[8][2];
            #pragma unroll
            for (int np = 0; np < 4; np++) {
                ldsm4(bf[2 * np][0], bf[2 * np][1],
                      bf[2 * np + 1][0], bf[2 * np + 1][1],
                      bS + ((wn * 64 + np * 16) * GPAD + ks) * 4 + offBP);
            }
            #pragma unroll
            for (int mt = 0; mt < 4; mt++)
                #pragma unroll
                for (int nt = 0; nt < 8; nt++)
                    mma_tf32(acc[mt][nt], af[mt], bf[nt][0], bf[nt][1]);
        }
    }

    // Epilogue: warp's 64-wide N range = one head of one q/k/v third
    const int nabs  = n0 + wn * 64;
    const int which = nabs >> 10;
    const int bq = m0 >> 11;
    const int t0 = m0 & (T_DIM - 1);
    const int h  = (nabs & 1023) >> 6;

    if (which < 2) {
        float* dst = (which == 0) ? g_q : g_k;
        const size_t rowbase = (size_t)(bq * H_DIM + h) * T_DIM;
        #pragma unroll
        for (int nt = 0; nt < 8; nt++) {
            const int d = nt * 8 + 2 * (lane & 3);
            const float2 bias = *(const float2*)(b + nabs + d);
            #pragma unroll
            for (int mt = 0; mt < 4; mt++) {
                const int t = t0 + wm * 64 + mt * 16 + (lane >> 2);
                float2 v0 = { __uint_as_float(f2tf(acc[mt][nt][0] + bias.x)),
                              __uint_as_float(f2tf(acc[mt][nt][1] + bias.y)) };
                float2 v1 = { __uint_as_float(f2tf(acc[mt][nt][2] + bias.x)),
                              __uint_as_float(f2tf(acc[mt][nt][3] + bias.y)) };
                *(float2*)(dst + (rowbase + t) * HD + d)     = v0;
                *(float2*)(dst + (rowbase + t + 8) * HD + d) = v1;
            }
        }
    } else {
        // V: transposed scatter to [B,H,D,T], time permuted within 8-blocks
        const size_t hb = (size_t)(bq * H_DIM + h) * HD;
        const int u  = lane >> 2;
        const int up = ((u & 1) << 2) | (u >> 1);      // PV-mma k permutation
        #pragma unroll
        for (int nt = 0; nt < 8; nt++) {
            const int d = nt * 8 + 2 * (lane & 3);
            const float2 bias = *(const float2*)(b + nabs + d);
            float* r0 = g_v + (hb + d)     * T_DIM;
            float* r1 = g_v + (hb + d + 1) * T_DIM;
            #pragma unroll
            for (int mt = 0; mt < 4; mt++) {
                const int t = t0 + wm * 64 + mt * 16 + up;
                r0[t]     = __uint_as_float(f2tf(acc[mt][nt][0] + bias.x));
                r1[t]     = __uint_as_float(f2tf(acc[mt][nt][1] + bias.y));
                r0[t + 8] = __uint_as_float(f2tf(acc[mt][nt][2] + bias.x));
                r1[t + 8] = __uint_as_float(f2tf(acc[mt][nt][3] + bias.y));
            }
        }
    }
}

// ---------------------------------------------------------------------------
// Flash attention: 256 q-rows/CTA, 8 warps x 32 rows, 256 threads.
// KV tiles of 64, double-buffered via cp.async; each staged tile feeds 2x
// the q-rows of round 12 (KV traffic + barrier iterations halved).
// P feeds PV mma directly from softmax registers; V pre-permuted.
// smem = Ks[2] + Vt[2] (Q staged through the WHOLE region pre-pipeline).
// ---------------------------------------------------------------------------
#define APAD 68
#define KV_U32 (64 * APAD)
#define SMEM_U32 (4 * KV_U32)          // Ks[2], Vt[2] == 256*APAD
#define ATTN_SMEM_BYTES (SMEM_U32 * 4) // 69632 B
#define QROWS 256
#define SC 0.1803368801111204f   // (1/8) * log2(e)

__global__ __launch_bounds__(256, 1) void attn_tf32(float* __restrict__ out)
{
    extern __shared__ uint32_t sm[];
    const uint32_t ksBase = smem_u32(sm);
    const uint32_t vtBase = ksBase + 2 * KV_U32 * 4;

    const int tid  = threadIdx.x;
    const int lane = tid & 31;
    const int warp = tid >> 5;                     // 0..7
    const int qt = (gridDim.x - 1) - blockIdx.x;   // heavy tiles first
    const int bh = blockIdx.y;

    const uint32_t offA = ((((lane & 7) + ((lane >> 3) & 1) * 8) * APAD)
                           + (lane >> 4) * 4) * 4;
    const uint32_t offB = (((lane & 7) * APAD) + (lane >> 3) * 4) * 4;

    const float* Qg  = g_q + (size_t)bh * T_DIM * HD;
    const float* Kg  = g_k + (size_t)bh * T_DIM * HD;
    const float* Vgt = g_v + (size_t)bh * HD * T_DIM;

    const int srow = tid >> 2;           // 0..63
    const int ch   = (tid & 3) * 16;     // 0,16,32,48
    const uint32_t kDst = ksBase + (srow * APAD + ch) * 4;
    const uint32_t vDst = vtBase + (srow * APAD + ch) * 4;

    // ---- stage Q (raw, pre-rounded) through the full smem region ----
    {
        const uint4* qp = (const uint4*)(Qg + (size_t)(qt * QROWS + tid) * HD);
        uint32_t qrow = ksBase + (tid * APAD) * 4;
        #pragma unroll
        for (int i = 0; i < 16; i++) {
            uint4 v = qp[i];
            asm volatile("st.shared.v4.b32 [%0], {%1,%2,%3,%4};"
                         :: "r"(qrow + i * 16), "r"(v.x), "r"(v.y),
                            "r"(v.z), "r"(v.w) : "memory");
        }
    }
    __syncthreads();
    uint32_t qa[2][8][4];
    #pragma unroll
    for (int mt = 0; mt < 2; mt++)
        #pragma unroll
        for (int k = 0; k < 8; k++)
            ldsm4(qa[mt][k][0], qa[mt][k][1], qa[mt][k][2], qa[mt][k][3],
                  ksBase + ((warp * 32 + mt * 16) * APAD + k * 8) * 4 + offA);
    __syncthreads();   // all qa reads done before smem is reused for K/V

    // ---- prologue: KV tile 0 in flight ----
    {
        const float* kp = Kg  + (size_t)srow * HD + ch;
        const float* vp = Vgt + (size_t)srow * T_DIM + ch;
        #pragma unroll
        for (int i = 0; i < 4; i++) {
            cp16(kDst + i * 16, kp + i * 4);
            cp16(vDst + i * 16, vp + i * 4);
        }
        CP_COMMIT();
    }

    float oa[2][8][4] = {};
    float mr[2][2] = {{-1e30f, -1e30f}, {-1e30f, -1e30f}};
    float lv[2][2] = {};
    const int rbase = qt * QROWS + warp * 32;
    const int NKV = 4 * qt + 4;

    for (int kt = 0; kt < NKV; kt++) {
        CP_WAIT0();
        __syncthreads();

        if (kt + 1 < NKV) {
            const int kn = kt + 1;
            const uint32_t bo = (uint32_t)(kn & 1) * (KV_U32 * 4);
            const float* kp = Kg  + (size_t)(kn * 64 + srow) * HD + ch;
            const float* vp = Vgt + (size_t)srow * T_DIM + kn * 64 + ch;
            #pragma unroll
            for (int i = 0; i < 4; i++) {
                cp16(kDst + bo + i * 16, kp + i * 4);
                cp16(vDst + bo + i * 16, vp + i * 4);
            }
        }
        CP_COMMIT();

        if (kt * 64 > rbase + 31) continue;   // fully masked for this warp

        const uint32_t bo = (uint32_t)(kt & 1) * (KV_U32 * 4);

        // ---- S = Q @ K^T ----
        float s[2][8][4] = {};
        #pragma unroll
        for (int kp2 = 0; kp2 < 4; kp2++) {
            #pragma unroll
            for (int j = 0; j < 8; j++) {
                uint32_t b0, b1, b2, b3;
                ldsm4(b0, b1, b2, b3,
                      ksBase + bo + ((j * 8) * APAD + kp2 * 16) * 4 + offB);
                mma_tf32(s[0][j], qa[0][2 * kp2],     b0, b1);
                mma_tf32(s[0][j], qa[0][2 * kp2 + 1], b2, b3);
                mma_tf32(s[1][j], qa[1][2 * kp2],     b0, b1);
                mma_tf32(s[1][j], qa[1][2 * kp2 + 1], b2, b3);
            }
        }

        // ---- causal mask (diagonal-overlapping tiles) ----
        if (kt * 64 + 63 > rbase) {
            #pragma unroll
            for (int mt = 0; mt < 2; mt++) {
                const int gr0 = rbase + mt * 16 + (lane >> 2);
                const int gr1 = gr0 + 8;
                #pragma unroll
                for (int j = 0; j < 8; j++) {
                    const int c0 = kt * 64 + j * 8 + 2 * (lane & 3);
                    if (c0     > gr0) s[mt][j][0] = -1e30f;
                    if (c0 + 1 > gr0) s[mt][j][1] = -1e30f;
                    if (c0     > gr1) s[mt][j][2] = -1e30f;
                    if (c0 + 1 > gr1) s[mt][j][3] = -1e30f;
                }
            }
        }

        // ---- online softmax (base-2, scale folded into ex2) ----
        #pragma unroll
        for (int mt = 0; mt < 2; mt++) {
            float mx0 = -1e30f, mx1 = -1e30f;
            #pragma unroll
            for (int j = 0; j < 8; j++) {
                mx0 = fmaxf(mx0, fmaxf(s[mt][j][0], s[mt][j][1]));
                mx1 = fmaxf(mx1, fmaxf(s[mt][j][2], s[mt][j][3]));
            }
            mx0 = fmaxf(mx0, __shfl_xor_sync(0xffffffff, mx0, 1));
            mx0 = fmaxf(mx0, __shfl_xor_sync(0xffffffff, mx0, 2));
            mx1 = fmaxf(mx1, __shfl_xor_sync(0xffffffff, mx1, 1));
            mx1 = fmaxf(mx1, __shfl_xor_sync(0xffffffff, mx1, 2));

            const float nm0 = fmaxf(mr[mt][0], mx0);
            const float nm1 = fmaxf(mr[mt][1], mx1);
            const float nm0c = nm0 * SC;
            const float nm1c = nm1 * SC;
            const float corr0 = ex2(fmaf(mr[mt][0], SC, -nm0c));
            const float corr1 = ex2(fmaf(mr[mt][1], SC, -nm1c));
            mr[mt][0] = nm0; mr[mt][1] = nm1;

            float sum0 = 0.0f, sum1 = 0.0f;
            #pragma unroll
            for (int j = 0; j < 8; j++) {
                s[mt][j][0] = ex2(fmaf(s[mt][j][0], SC, -nm0c)); sum0 += s[mt][j][0];
                s[mt][j][1] = ex2(fmaf(s[mt][j][1], SC, -nm0c)); sum0 += s[mt][j][1];
                s[mt][j][2] = ex2(fmaf(s[mt][j][2], SC, -nm1c)); sum1 += s[mt][j][2];
                s[mt][j][3] = ex2(fmaf(s[mt][j][3], SC, -nm1c)); sum1 += s[mt][j][3];
            }
            sum0 += __shfl_xor_sync(0xffffffff, sum0, 1);
            sum0 += __shfl_xor_sync(0xffffffff, sum0, 2);
            sum1 += __shfl_xor_sync(0xffffffff, sum1, 1);
            sum1 += __shfl_xor_sync(0xffffffff, sum1, 2);
            lv[mt][0] = lv[mt][0] * corr0 + sum0;
            lv[mt][1] = lv[mt][1] * corr1 + sum1;

            #pragma unroll
            for (int j = 0; j < 8; j++) {
                oa[mt][j][0] *= corr0; oa[mt][j][1] *= corr0;
                oa[mt][j][2] *= corr1; oa[mt][j][3] *= corr1;
            }
        }

        // ---- O += P @ V : A-frags straight from softmax registers ----
        #pragma unroll
        for (int kp2 = 0; kp2 < 4; kp2++) {
            uint32_t A0[2][4], A1[2][4];
            #pragma unroll
            for (int mt = 0; mt < 2; mt++) {
                A0[mt][0] = f2tf(s[mt][2 * kp2][0]);
                A0[mt][1] = f2tf(s[mt][2 * kp2][2]);
                A0[mt][2] = f2tf(s[mt][2 * kp2][1]);
                A0[mt][3] = f2tf(s[mt][2 * kp2][3]);
                A1[mt][0] = f2tf(s[mt][2 * kp2 + 1][0]);
                A1[mt][1] = f2tf(s[mt][2 * kp2 + 1][2]);
                A1[mt][2] = f2tf(s[mt][2 * kp2 + 1][1]);
                A1[mt][3] = f2tf(s[mt][2 * kp2 + 1][3]);
            }
            #pragma unroll
            for (int j = 0; j < 8; j++) {
                uint32_t b0, b1, b2, b3;
                ldsm4(b0, b1, b2, b3,
                      vtBase + bo + ((j * 8) * APAD + kp2 * 16) * 4 + offB);
                mma_tf32(oa[0][j], A0[0], b0, b1);
                mma_tf32(oa[0][j], A1[0], b2, b3);
                mma_tf32(oa[1][j], A0[1], b0, b1);
                mma_tf32(oa[1][j], A1[1], b2, b3);
            }
        }
    }

    // ---- epilogue: normalize, write [B,T,C] ----
    const int bq = bh >> 4;
    const int h  = bh & 15;
    #pragma unroll
    for (int mt = 0; mt < 2; mt++) {
        const float inv0 = 1.0f / lv[mt][0];
        const float inv1 = 1.0f / lv[mt][1];
        const int trow = rbase + mt * 16 + (lane >> 2);
        #pragma unroll
        for (int j = 0; j < 8; j++) {
            const int d = j * 8 + 2 * (lane & 3);
            float2 v0 = { oa[mt][j][0] * inv0, oa[mt][j][1] * inv0 };
            float2 v1 = { oa[mt][j][2] * inv1, oa[mt][j][3] * inv1 };
            *(float2*)(out + (size_t)(bq * T_DIM + trow) * C_DIM + h * HD + d)     = v0;
            *(float2*)(out + (size_t)(bq * T_DIM + trow + 8) * C_DIM + h * HD + d) = v1;
        }
    }
}

// ---------------------------------------------------------------------------
extern "C" void kernel_launch(void* const* d_in, const int* in_sizes, int n_in,
                              void* d_out, int out_size)
{
    const float* x = (const float*)d_in[0];   // [4, 2048, 1024]
    const float* W = (const float*)d_in[1];   // [3072, 1024]
    const float* b = (const float*)d_in[2];   // [3072]
    float* out = (float*)d_out;               // [4, 2048, 1024]

    cudaFuncSetAttribute(qkv_gemm_tf32, cudaFuncAttributeMaxDynamicSharedMemorySize,
                         GEMM_SMEM_BYTES);
    cudaFuncSetAttribute(attn_tf32, cudaFuncAttributeMaxDynamicSharedMemorySize,
                         ATTN_SMEM_BYTES);

    const size_t ncvt = ((size_t)M_TOT * C_DIM + (size_t)N_TOT * C_DIM) / 4;
    cvt_pre<<<(unsigned)((ncvt + 255) / 256), 256>>>(x, W);
    qkv_gemm_tf32<<<dim3(N_TOT / 128, M_TOT / 128), 128, GEMM_SMEM_BYTES>>>(b);
    attn_tf32<<<dim3(T_DIM / QROWS, B_DIM * H_DIM), 256, ATTN_SMEM_BYTES>>>(out);
}

// round 14
// speedup vs baseline: 1.0920x; 1.0920x over previous
#include <cuda_runtime.h>
#include <cstdint>

#define C_DIM 1024
#define B_DIM 4
#define T_DIM 2048
#define H_DIM 16
#define HD    64
#define M_TOT (B_DIM * T_DIM)   // 8192
#define N_TOT (3 * C_DIM)       // 3072

// Q/K in [B,H,T,D]; V TRANSPOSED in [B,H,D,T] with time-index permuted
// within each 8-block (PV-mma layout). All tf32-rounded fp32 bits.
__device__ float g_q[(size_t)M_TOT * C_DIM];
__device__ float g_k[(size_t)M_TOT * C_DIM];
__device__ float g_v[(size_t)M_TOT * C_DIM];
// tf32-rounded copies of inputs
__device__ float g_xt[(size_t)M_TOT * C_DIM];
__device__ float g_wt[(size_t)N_TOT * C_DIM];

__device__ __forceinline__ uint32_t f2tf(float f) {
    uint32_t u;
    asm("cvt.rna.tf32.f32 %0, %1;" : "=r"(u) : "f"(f));
    return u;
}

__device__ __forceinline__ float ex2(float x) {
    float y;
    asm("ex2.approx.f32 %0, %1;" : "=f"(y) : "f"(x));
    return y;
}

__device__ __forceinline__ void mma_tf32(float c[4], const uint32_t a[4],
                                         uint32_t b0, uint32_t b1) {
    asm volatile(
        "mma.sync.aligned.m16n8k8.row.col.f32.tf32.tf32.f32 "
        "{%0,%1,%2,%3}, {%4,%5,%6,%7}, {%8,%9}, {%0,%1,%2,%3};"
        : "+f"(c[0]), "+f"(c[1]), "+f"(c[2]), "+f"(c[3])
        : "r"(a[0]), "r"(a[1]), "r"(a[2]), "r"(a[3]), "r"(b0), "r"(b1));
}

__device__ __forceinline__ void ldsm4(uint32_t& d0, uint32_t& d1,
                                      uint32_t& d2, uint32_t& d3,
                                      uint32_t addr) {
    asm volatile("ldmatrix.sync.aligned.m8n8.x4.shared.b16 {%0,%1,%2,%3}, [%4];"
                 : "=r"(d0), "=r"(d1), "=r"(d2), "=r"(d3) : "r"(addr));
}

__device__ __forceinline__ uint32_t smem_u32(const void* p) {
    uint32_t a;
    asm("{ .reg .u64 t; cvta.to.shared.u64 t, %1; cvt.u32.u64 %0, t; }"
        : "=r"(a) : "l"(p));
    return a;
}

__device__ __forceinline__ void cp16(uint32_t dst, const void* src) {
    asm volatile("cp.async.cg.shared.global [%0], [%1], 16;"
                 :: "r"(dst), "l"(src));
}
#define CP_COMMIT() asm volatile("cp.async.commit_group;" ::: "memory")
#define CP_WAIT0()  asm volatile("cp.async.wait_group 0;" ::: "memory")

// ---------------------------------------------------------------------------
// Prepass: tf32-round (rna) x and W into scratch copies.
// ---------------------------------------------------------------------------
__global__ __launch_bounds__(256) void cvt_pre(
    const float* __restrict__ x, const float* __restrict__ W)
{
    const size_t nx = (size_t)M_TOT * C_DIM / 4;
    const size_t nw = (size_t)N_TOT * C_DIM / 4;
    size_t i = (size_t)blockIdx.x * blockDim.x + threadIdx.x;
    if (i < nx) {
        float4 v = ((const float4*)x)[i];
        uint4 u = { f2tf(v.x), f2tf(v.y), f2tf(v.z), f2tf(v.w) };
        ((uint4*)g_xt)[i] = u;
    } else if (i < nx + nw) {
        float4 v = ((const float4*)W)[i - nx];
        uint4 u = { f2tf(v.x), f2tf(v.y), f2tf(v.z), f2tf(v.w) };
        ((uint4*)g_wt)[i - nx] = u;
    }
}

// ---------------------------------------------------------------------------
// QKV GEMM: CTA 128x128, 8 warps (2Mx4N), warp tile 64x32 (round-12 proven).
// 4 stages = 2 double-buffered PAIRS; 2 k-tiles per barrier (32 barriers).
// Q/K scattered (tf32-rounded) to [B,H,T,D]; V transposed to [B,H,D,T]
// with time index PERMUTED within each 8-block: t' = ((t&1)<<2)|((t&7)>>1).
// ---------------------------------------------------------------------------
#define GPAD 20
#define GSTAGE_U32 (128 * GPAD)
#define GEMM_SMEM_BYTES (8 * GSTAGE_U32 * 4)   // (A+B) x 4 stages = 81920 B

__global__ __launch_bounds__(256, 2) void qkv_gemm_tf32(
    const float* __restrict__ b)
{
    extern __shared__ uint32_t gsm[];
    uint32_t* Abuf = gsm;                     // [4][128][GPAD]
    uint32_t* Bbuf = gsm + 4 * GSTAGE_U32;    // [4][128][GPAD]

    const int tid  = threadIdx.x;
    const int lane = tid & 31;
    const int warp = tid >> 5;
    const int wm = warp >> 2;
    const int wn = warp & 3;
    const int m0 = blockIdx.y * 128;
    const int n0 = blockIdx.x * 128;

    const uint32_t aBase = smem_u32(Abuf);
    const uint32_t bBase = smem_u32(Bbuf);

    const uint32_t offA = ((((lane & 7) + ((lane >> 3) & 1) * 8) * GPAD)
                           + (lane >> 4) * 4) * 4;
    const uint32_t offBP = ((((lane & 7) + (lane >> 4) * 8) * GPAD)
                            + ((lane >> 3) & 1) * 4) * 4;

    const int lrow = tid >> 1;
    const int lcol = (tid & 1) * 8;
    const float* ap = g_xt + (size_t)(m0 + lrow) * C_DIM + lcol;
    const float* bp = g_wt + (size_t)(n0 + lrow) * C_DIM + lcol;
    const uint32_t aDst = aBase + (lrow * GPAD + lcol) * 4;
    const uint32_t bDst = bBase + (lrow * GPAD + lcol) * 4;

    float acc[4][4][4] = {};

    // prologue: pair 0 (k-tiles 0,1 -> stages 0,1), one commit group
    #pragma unroll
    for (int t = 0; t < 2; t++) {
        const uint32_t so = (uint32_t)t * (GSTAGE_U32 * 4);
        cp16(aDst + so, ap + t * 16);
        cp16(aDst + so + 16, ap + t * 16 + 4);
        cp16(bDst + so, bp + t * 16);
        cp16(bDst + so + 16, bp + t * 16 + 4);
    }
    CP_COMMIT();

    #pragma unroll 1
    for (int pi = 0; pi < 32; pi++) {
        const int kt0 = pi * 2;
        CP_WAIT0();          // pair pi landed
        __syncthreads();     // all warps past reads of the other pair's stages

        // issue pair pi+1 into the other stage pair (disjoint from compute)
        if (pi < 31) {
            #pragma unroll
            for (int t = 0; t < 2; t++) {
                const int kn = kt0 + 2 + t;
                const uint32_t so = (uint32_t)(kn & 3) * (GSTAGE_U32 * 4);
                cp16(aDst + so, ap + kn * 16);
                cp16(aDst + so + 16, ap + kn * 16 + 4);
                cp16(bDst + so, bp + kn * 16);
                cp16(bDst + so + 16, bp + kn * 16 + 4);
            }
        }
        CP_COMMIT();

        // compute both k-tiles of pair pi
        #pragma unroll
        for (int t = 0; t < 2; t++) {
            const uint32_t soff = (uint32_t)((kt0 + t) & 3) * (GSTAGE_U32 * 4);
            #pragma unroll
            for (int ks = 0; ks < 16; ks += 8) {
                uint32_t af[4][4];
                #pragma unroll
                for (int mt = 0; mt < 4; mt++) {
                    ldsm4(af[mt][0], af[mt][1], af[mt][2], af[mt][3],
                          aBase + soff + ((wm * 64 + mt * 16) * GPAD + ks) * 4 + offA);
                }
                uint32_t bf[4][2];
                ldsm4(bf[0][0], bf[0][1], bf[1][0], bf[1][1],
                      bBase + soff + ((wn * 32) * GPAD + ks) * 4 + offBP);
                ldsm4(bf[2][0], bf[2][1], bf[3][0], bf[3][1],
                      bBase + soff + ((wn * 32 + 16) * GPAD + ks) * 4 + offBP);
                #pragma unroll
                for (int mt = 0; mt < 4; mt++)
                    #pragma unroll
                    for (int nt = 0; nt < 4; nt++)
                        mma_tf32(acc[mt][nt], af[mt], bf[nt][0], bf[nt][1]);
            }
        }
    }

    const int which = n0 >> 10;
    const int bq = m0 >> 11;
    const int t0 = m0 & (T_DIM - 1);
    const int h  = (((n0 & 1023) + wn * 32) >> 6);

    if (which < 2) {
        float* dst = (which == 0) ? g_q : g_k;
        #pragma unroll
        for (int nt = 0; nt < 4; nt++) {
            const int ncol = wn * 32 + nt * 8 + 2 * (lane & 3);
            const float2 bias = *(const float2*)(b + n0 + ncol);
            const int d = ncol & 63;
            const size_t rowbase = (size_t)(bq * H_DIM + h) * T_DIM;
            #pragma unroll
            for (int mt = 0; mt < 4; mt++) {
                const int t = t0 + wm * 64 + mt * 16 + (lane >> 2);
                float2 v0 = { __uint_as_float(f2tf(acc[mt][nt][0] + bias.x)),
                              __uint_as_float(f2tf(acc[mt][nt][1] + bias.y)) };
                float2 v1 = { __uint_as_float(f2tf(acc[mt][nt][2] + bias.x)),
                              __uint_as_float(f2tf(acc[mt][nt][3] + bias.y)) };
                *(float2*)(dst + (rowbase + t) * HD + d)     = v0;
                *(float2*)(dst + (rowbase + t + 8) * HD + d) = v1;
            }
        }
    } else {
        // V: transposed scatter to [B,H,D,T], time permuted within 8-blocks
        const size_t hb = (size_t)(bq * H_DIM + h) * HD;
        const int u  = lane >> 2;                      // 0..7
        const int up = ((u & 1) << 2) | (u >> 1);      // PV-mma k permutation
        #pragma unroll
        for (int nt = 0; nt < 4; nt++) {
            const int ncol = wn * 32 + nt * 8 + 2 * (lane & 3);
            const float2 bias = *(const float2*)(b + n0 + ncol);
            const int d = ncol & 63;
            float* r0 = g_v + (hb + d)     * T_DIM;
            float* r1 = g_v + (hb + d + 1) * T_DIM;
            #pragma unroll
            for (int mt = 0; mt < 4; mt++) {
                const int t = t0 + wm * 64 + mt * 16 + up;
                r0[t]     = __uint_as_float(f2tf(acc[mt][nt][0] + bias.x));
                r1[t]     = __uint_as_float(f2tf(acc[mt][nt][1] + bias.y));
                r0[t + 8] = __uint_as_float(f2tf(acc[mt][nt][2] + bias.x));
                r1[t + 8] = __uint_as_float(f2tf(acc[mt][nt][3] + bias.y));
            }
        }
    }
}

// ---------------------------------------------------------------------------
// Flash attention: 128 q-rows/CTA, 4 warps x 32 rows. KV tiles of 64,
// double-buffered via cp.async. P feeds PV mma DIRECTLY from softmax
// registers (A = {s0,s2,s1,s3}); V is pre-permuted to match. No Ps buffer:
// smem = Ks[2] + Vt[2] only (Q staged through the Vt region pre-pipeline).
// (byte-identical to round 12 — known good)
// ---------------------------------------------------------------------------
#define APAD 68
#define KV_U32 (64 * APAD)
#define SMEM_U32 (4 * KV_U32)          // Ks[2], Vt[2]
#define ATTN_SMEM_BYTES (SMEM_U32 * 4) // 69632 B
#define SC 0.1803368801111204f   // (1/8) * log2(e)

__global__ __launch_bounds__(128, 2) void attn_tf32(float* __restrict__ out)
{
    extern __shared__ uint32_t sm[];
    const uint32_t ksBase = smem_u32(sm);
    const uint32_t vtBase = ksBase + 2 * KV_U32 * 4;

    const int tid  = threadIdx.x;
    const int lane = tid & 31;
    const int warp = tid >> 5;
    const int qt = (gridDim.x - 1) - blockIdx.x;   // heavy tiles first
    const int bh = blockIdx.y;

    const uint32_t offA = ((((lane & 7) + ((lane >> 3) & 1) * 8) * APAD)
                           + (lane >> 4) * 4) * 4;
    const uint32_t offB = (((lane & 7) * APAD) + (lane >> 3) * 4) * 4;

    const float* Qg  = g_q + (size_t)bh * T_DIM * HD;
    const float* Kg  = g_k + (size_t)bh * T_DIM * HD;
    const float* Vgt = g_v + (size_t)bh * HD * T_DIM;

    const int srow = tid >> 1;           // 0..63
    const int ch   = (tid & 1) * 32;     // 0 or 32
    const uint32_t kDst = ksBase + (srow * APAD + ch) * 4;
    const uint32_t vDst = vtBase + (srow * APAD + ch) * 4;

    // ---- stage Q (raw, pre-rounded) through the Vt[2] region, pull qa ----
    {
        const uint4* qp = (const uint4*)(Qg + (size_t)(qt * 128 + tid) * HD);
        uint32_t qrow = vtBase + (tid * APAD) * 4;
        #pragma unroll
        for (int i = 0; i < 16; i++) {
            uint4 v = qp[i];
            asm volatile("st.shared.v4.b32 [%0], {%1,%2,%3,%4};"
                         :: "r"(qrow + i * 16), "r"(v.x), "r"(v.y),
                            "r"(v.z), "r"(v.w) : "memory");
        }
    }
    __syncthreads();
    uint32_t qa[2][8][4];
    #pragma unroll
    for (int mt = 0; mt < 2; mt++)
        #pragma unroll
        for (int k = 0; k < 8; k++)
            ldsm4(qa[mt][k][0], qa[mt][k][1], qa[mt][k][2], qa[mt][k][3],
                  vtBase + ((warp * 32 + mt * 16) * APAD + k * 8) * 4 + offA);
    __syncthreads();   // all qa reads done before Vt is reused for V

    // ---- prologue: KV tile 0 in flight ----
    {
        const float* kp = Kg  + (size_t)srow * HD + ch;
        const float* vp = Vgt + (size_t)srow * T_DIM + ch;
        #pragma unroll
        for (int i = 0; i < 8; i++) {
            cp16(kDst + i * 16, kp + i * 4);
            cp16(vDst + i * 16, vp + i * 4);
        }
        CP_COMMIT();
    }

    float oa[2][8][4] = {};
    float mr[2][2] = {{-1e30f, -1e30f}, {-1e30f, -1e30f}};
    float lv[2][2] = {};
    const int rbase = qt * 128 + warp * 32;
    const int NKV = 2 * qt + 2;

    for (int kt = 0; kt < NKV; kt++) {
        CP_WAIT0();
        __syncthreads();

        if (kt + 1 < NKV) {
            const int kn = kt + 1;
            const uint32_t bo = (uint32_t)(kn & 1) * (KV_U32 * 4);
            const float* kp = Kg  + (size_t)(kn * 64 + srow) * HD + ch;
            const float* vp = Vgt + (size_t)srow * T_DIM + kn * 64 + ch;
            #pragma unroll
            for (int i = 0; i < 8; i++) {
                cp16(kDst + bo + i * 16, kp + i * 4);
                cp16(vDst + bo + i * 16, vp + i * 4);
            }
        }
        CP_COMMIT();

        if (kt * 64 > rbase + 31) continue;

        const uint32_t bo = (uint32_t)(kt & 1) * (KV_U32 * 4);

        // ---- S = Q @ K^T ----
        float s[2][8][4] = {};
        #pragma unroll
        for (int kp2 = 0; kp2 < 4; kp2++) {
            #pragma unroll
            for (int j = 0; j < 8; j++) {
                uint32_t b0, b1, b2, b3;
                ldsm4(b0, b1, b2, b3,
                      ksBase + bo + ((j * 8) * APAD + kp2 * 16) * 4 + offB);
                mma_tf32(s[0][j], qa[0][2 * kp2],     b0, b1);
                mma_tf32(s[0][j], qa[0][2 * kp2 + 1], b2, b3);
                mma_tf32(s[1][j], qa[1][2 * kp2],     b0, b1);
                mma_tf32(s[1][j], qa[1][2 * kp2 + 1], b2, b3);
            }
        }

        // ---- causal mask (diagonal-overlapping tiles) ----
        if (kt * 64 + 63 > rbase) {
            #pragma unroll
            for (int mt = 0; mt < 2; mt++) {
                const int gr0 = rbase + mt * 16 + (lane >> 2);
                const int gr1 = gr0 + 8;
                #pragma unroll
                for (int j = 0; j < 8; j++) {
                    const int c0 = kt * 64 + j * 8 + 2 * (lane & 3);
                    if (c0     > gr0) s[mt][j][0] = -1e30f;
                    if (c0 + 1 > gr0) s[mt][j][1] = -1e30f;
                    if (c0     > gr1) s[mt][j][2] = -1e30f;
                    if (c0 + 1 > gr1) s[mt][j][3] = -1e30f;
                }
            }
        }

        // ---- online softmax (base-2, scale folded into ex2) ----
        #pragma unroll
        for (int mt = 0; mt < 2; mt++) {
            float mx0 = -1e30f, mx1 = -1e30f;
            #pragma unroll
            for (int j = 0; j < 8; j++) {
                mx0 = fmaxf(mx0, fmaxf(s[mt][j][0], s[mt][j][1]));
                mx1 = fmaxf(mx1, fmaxf(s[mt][j][2], s[mt][j][3]));
            }
            mx0 = fmaxf(mx0, __shfl_xor_sync(0xffffffff, mx0, 1));
            mx0 = fmaxf(mx0, __shfl_xor_sync(0xffffffff, mx0, 2));
            mx1 = fmaxf(mx1, __shfl_xor_sync(0xffffffff, mx1, 1));
            mx1 = fmaxf(mx1, __shfl_xor_sync(0xffffffff, mx1, 2));

            const float nm0 = fmaxf(mr[mt][0], mx0);
            const float nm1 = fmaxf(mr[mt][1], mx1);
            const float nm0c = nm0 * SC;
            const float nm1c = nm1 * SC;
            const float corr0 = ex2(fmaf(mr[mt][0], SC, -nm0c));
            const float corr1 = ex2(fmaf(mr[mt][1], SC, -nm1c));
            mr[mt][0] = nm0; mr[mt][1] = nm1;

            float sum0 = 0.0f, sum1 = 0.0f;
            #pragma unroll
            for (int j = 0; j < 8; j++) {
                s[mt][j][0] = ex2(fmaf(s[mt][j][0], SC, -nm0c)); sum0 += s[mt][j][0];
                s[mt][j][1] = ex2(fmaf(s[mt][j][1], SC, -nm0c)); sum0 += s[mt][j][1];
                s[mt][j][2] = ex2(fmaf(s[mt][j][2], SC, -nm1c)); sum1 += s[mt][j][2];
                s[mt][j][3] = ex2(fmaf(s[mt][j][3], SC, -nm1c)); sum1 += s[mt][j][3];
            }
            sum0 += __shfl_xor_sync(0xffffffff, sum0, 1);
            sum0 += __shfl_xor_sync(0xffffffff, sum0, 2);
            sum1 += __shfl_xor_sync(0xffffffff, sum1, 1);
            sum1 += __shfl_xor_sync(0xffffffff, sum1, 2);
            lv[mt][0] = lv[mt][0] * corr0 + sum0;
            lv[mt][1] = lv[mt][1] * corr1 + sum1;

            #pragma unroll
            for (int j = 0; j < 8; j++) {
                oa[mt][j][0] *= corr0; oa[mt][j][1] *= corr0;
                oa[mt][j][2] *= corr1; oa[mt][j][3] *= corr1;
            }
        }

        // ---- O += P @ V : A-frags straight from softmax registers ----
        #pragma unroll
        for (int kp2 = 0; kp2 < 4; kp2++) {
            uint32_t A0[2][4], A1[2][4];
            #pragma unroll
            for (int mt = 0; mt < 2; mt++) {
                A0[mt][0] = f2tf(s[mt][2 * kp2][0]);
                A0[mt][1] = f2tf(s[mt][2 * kp2][2]);
                A0[mt][2] = f2tf(s[mt][2 * kp2][1]);
                A0[mt][3] = f2tf(s[mt][2 * kp2][3]);
                A1[mt][0] = f2tf(s[mt][2 * kp2 + 1][0]);
                A1[mt][1] = f2tf(s[mt][2 * kp2 + 1][2]);
                A1[mt][2] = f2tf(s[mt][2 * kp2 + 1][1]);
                A1[mt][3] = f2tf(s[mt][2 * kp2 + 1][3]);
            }
            #pragma unroll
            for (int j = 0; j < 8; j++) {
                uint32_t b0, b1, b2, b3;
                ldsm4(b0, b1, b2, b3,
                      vtBase + bo + ((j * 8) * APAD + kp2 * 16) * 4 + offB);
                mma_tf32(oa[0][j], A0[0], b0, b1);
                mma_tf32(oa[0][j], A1[0], b2, b3);
                mma_tf32(oa[1][j], A0[1], b0, b1);
                mma_tf32(oa[1][j], A1[1], b2, b3);
            }
        }
    }

    // ---- epilogue: normalize, write [B,T,C] ----
    const int bq = bh >> 4;
    const int h  = bh & 15;
    #pragma unroll
    for (int mt = 0; mt < 2; mt++) {
        const float inv0 = 1.0f / lv[mt][0];
        const float inv1 = 1.0f / lv[mt][1];
        const int trow = rbase + mt * 16 + (lane >> 2);
        #pragma unroll
        for (int j = 0; j < 8; j++) {
            const int d = j * 8 + 2 * (lane & 3);
            float2 v0 = { oa[mt][j][0] * inv0, oa[mt][j][1] * inv0 };
            float2 v1 = { oa[mt][j][2] * inv1, oa[mt][j][3] * inv1 };
            *(float2*)(out + (size_t)(bq * T_DIM + trow) * C_DIM + h * HD + d)     = v0;
            *(float2*)(out + (size_t)(bq * T_DIM + trow + 8) * C_DIM + h * HD + d) = v1;
        }
    }
}

// ---------------------------------------------------------------------------
extern "C" void kernel_launch(void* const* d_in, const int* in_sizes, int n_in,
                              void* d_out, int out_size)
{
    const float* x = (const float*)d_in[0];   // [4, 2048, 1024]
    const float* W = (const float*)d_in[1];   // [3072, 1024]
    const float* b = (const float*)d_in[2];   // [3072]
    float* out = (float*)d_out;               // [4, 2048, 1024]

    cudaFuncSetAttribute(qkv_gemm_tf32, cudaFuncAttributeMaxDynamicSharedMemorySize,
                         GEMM_SMEM_BYTES);
    cudaFuncSetAttribute(attn_tf32, cudaFuncAttributeMaxDynamicSharedMemorySize,
                         ATTN_SMEM_BYTES);

    const size_t ncvt = ((size_t)M_TOT * C_DIM + (size_t)N_TOT * C_DIM) / 4;
    cvt_pre<<<(unsigned)((ncvt + 255) / 256), 256>>>(x, W);
    qkv_gemm_tf32<<<dim3(N_TOT / 128, M_TOT / 128), 256, GEMM_SMEM_BYTES>>>(b);
    attn_tf32<<<dim3(T_DIM / 128, B_DIM * H_DIM), 128, ATTN_SMEM_BYTES>>>(out);
}

// round 16
// speedup vs baseline: 2.0935x; 1.9171x over previous
#include <cuda_runtime.h>
#include <cuda_fp16.h>
#include <cstdint>

#define C_DIM 1024
#define B_DIM 4
#define T_DIM 2048
#define H_DIM 16
#define HD    64
#define M_TOT (B_DIM * T_DIM)   // 8192
#define N_TOT (3 * C_DIM)       // 3072

// Q/K in [B,H,T,D] halves; V TRANSPOSED in [B,H,D,T] halves.
__device__ __align__(16) __half g_qh[(size_t)M_TOT * C_DIM];
__device__ __align__(16) __half g_kh[(size_t)M_TOT * C_DIM];
__device__ __align__(16) __half g_vh[(size_t)M_TOT * C_DIM];
// f16 copies of inputs
__device__ __align__(16) __half g_xt[(size_t)M_TOT * C_DIM];
__device__ __align__(16) __half g_wt[(size_t)N_TOT * C_DIM];

__device__ __forceinline__ float ex2(float x) {
    float y;
    asm("ex2.approx.f32 %0, %1;" : "=f"(y) : "f"(x));
    return y;
}

// pack two f32 -> f16x2 (lo in low half). cvt.rn.f16x2.f32 d, a, b => d = {hi=a, lo=b}
__device__ __forceinline__ uint32_t packh2(float lo, float hi) {
    uint32_t d;
    asm("cvt.rn.f16x2.f32 %0, %1, %2;" : "=r"(d) : "f"(hi), "f"(lo));
    return d;
}

__device__ __forceinline__ void mma16816(float c[4], const uint32_t a[4],
                                         uint32_t b0, uint32_t b1) {
    asm volatile(
        "mma.sync.aligned.m16n8k16.row.col.f32.f16.f16.f32 "
        "{%0,%1,%2,%3}, {%4,%5,%6,%7}, {%8,%9}, {%0,%1,%2,%3};"
        : "+f"(c[0]), "+f"(c[1]), "+f"(c[2]), "+f"(c[3])
        : "r"(a[0]), "r"(a[1]), "r"(a[2]), "r"(a[3]), "r"(b0), "r"(b1));
}

__device__ __forceinline__ void ldsm4(uint32_t& d0, uint32_t& d1,
                                      uint32_t& d2, uint32_t& d3,
                                      uint32_t addr) {
    asm volatile("ldmatrix.sync.aligned.m8n8.x4.shared.b16 {%0,%1,%2,%3}, [%4];"
                 : "=r"(d0), "=r"(d1), "=r"(d2), "=r"(d3) : "r"(addr));
}

__device__ __forceinline__ uint32_t smem_u32(const void* p) {
    uint32_t a;
    asm("{ .reg .u64 t; cvta.to.shared.u64 t, %1; cvt.u32.u64 %0, t; }"
        : "=r"(a) : "l"(p));
    return a;
}

__device__ __forceinline__ void cp16(uint32_t dst, const void* src) {
    asm volatile("cp.async.cg.shared.global [%0], [%1], 16;"
                 :: "r"(dst), "l"(src));
}
#define CP_COMMIT() asm volatile("cp.async.commit_group;" ::: "memory")
#define CP_WAIT0()  asm volatile("cp.async.wait_group 0;" ::: "memory")

// ---------------------------------------------------------------------------
// Prepass: fp32 -> f16 copies of x and W. One thread = 8 elements.
// ---------------------------------------------------------------------------
__global__ __launch_bounds__(256) void cvt_pre(
    const float* __restrict__ x, const float* __restrict__ W)
{
    const size_t nx = (size_t)M_TOT * C_DIM / 8;   // 1048576
    const size_t nw = (size_t)N_TOT * C_DIM / 8;   // 393216
    size_t i = (size_t)blockIdx.x * blockDim.x + threadIdx.x;
    if (i < nx) {
        float4 v0 = ((const float4*)x)[2 * i];
        float4 v1 = ((const float4*)x)[2 * i + 1];
        uint4 u = { packh2(v0.x, v0.y), packh2(v0.z, v0.w),
                    packh2(v1.x, v1.y), packh2(v1.z, v1.w) };
        ((uint4*)g_xt)[i] = u;
    } else if (i < nx + nw) {
        const size_t j = i - nx;
        float4 v0 = ((const float4*)W)[2 * j];
        float4 v1 = ((const float4*)W)[2 * j + 1];
        uint4 u = { packh2(v0.x, v0.y), packh2(v0.z, v0.w),
                    packh2(v1.x, v1.y), packh2(v1.z, v1.w) };
        ((uint4*)g_wt)[i - nx] = u;
    }
}

// ---------------------------------------------------------------------------
// QKV GEMM (f16 mma m16n8k16): CTA 128x128, 8 warps (2Mx4N), warp 64x32.
// k-tile 32, 4-stage cp.async ring processed in PAIRS (16 barriers).
// Rows = 32 halves padded to KP=40 (80B stride: 16B-aligned, conflict-free
// — same 20-word bank geometry as the proven tf32 GPAD=20 layout).
// Q/K scattered to [B,H,T,D] halves; V transposed to [B,H,D,T] halves.
// ---------------------------------------------------------------------------
#define KP 40
#define GST_B (128 * KP * 2)                 // 10240 bytes per matrix stage
#define GEMM_SMEM_BYTES (8 * GST_B)          // A[4] + B[4] = 81920 B

__global__ __launch_bounds__(256, 2) void qkv_gemm_f16(
    const float* __restrict__ b)
{
    extern __shared__ char gsm[];
    const uint32_t aBase = smem_u32(gsm);
    const uint32_t bBase = aBase + 4 * GST_B;

    const int tid  = threadIdx.x;
    const int lane = tid & 31;
    const int warp = tid >> 5;
    const int wm = warp >> 2;          // 0..1
    const int wn = warp & 3;           // 0..3
    const int m0 = blockIdx.y * 128;
    const int n0 = blockIdx.x * 128;

    // ldsm lane offsets (bytes), rows of KP halves
    const uint32_t offA = ((((lane & 7) + ((lane >> 3) & 1) * 8) * KP)
                           + (lane >> 4) * 8) * 2;
    const uint32_t offB = ((((lane & 7) + (lane >> 4) * 8) * KP)
                           + ((lane >> 3) & 1) * 8) * 2;

    // staging: thread t covers row t>>1, 16-half chunk (t&1)
    const int lrow = tid >> 1;
    const int lch  = (tid & 1) * 16;   // halves
    const __half* ap = g_xt + (size_t)(m0 + lrow) * C_DIM + lch;
    const __half* bp = g_wt + (size_t)(n0 + lrow) * C_DIM + lch;
    const uint32_t aDst = aBase + (lrow * KP + lch) * 2;
    const uint32_t bDst = bBase + (lrow * KP + lch) * 2;

    float acc[4][4][4] = {};

    // prologue: pair 0 (k-tiles 0,1 -> stages 0,1)
    #pragma unroll
    for (int t = 0; t < 2; t++) {
        const uint32_t so = (uint32_t)t * GST_B;
        cp16(aDst + so,      ap + t * 32);
        cp16(aDst + so + 16, ap + t * 32 + 8);
        cp16(bDst + so,      bp + t * 32);
        cp16(bDst + so + 16, bp + t * 32 + 8);
    }
    CP_COMMIT();

    #pragma unroll 1
    for (int pi = 0; pi < 16; pi++) {
        const int kt0 = pi * 2;
        CP_WAIT0();
        __syncthreads();

        if (pi < 15) {
            #pragma unroll
            for (int t = 0; t < 2; t++) {
                const int kn = kt0 + 2 + t;
                const uint32_t so = (uint32_t)(kn & 3) * GST_B;
                cp16(aDst + so,      ap + kn * 32);
                cp16(aDst + so + 16, ap + kn * 32 + 8);
                cp16(bDst + so,      bp + kn * 32);
                cp16(bDst + so + 16, bp + kn * 32 + 8);
            }
        }
        CP_COMMIT();

        #pragma unroll
        for (int t = 0; t < 2; t++) {
            const uint32_t aS = aBase + (uint32_t)((kt0 + t) & 3) * GST_B;
            const uint32_t bS = bBase + (uint32_t)((kt0 + t) & 3) * GST_B;
            #pragma unroll
            for (int c = 0; c < 2; c++) {          // k16 chunk
                uint32_t af[4][4];
                #pragma unroll
                for (int mt = 0; mt < 4; mt++) {
                    ldsm4(af[mt][0], af[mt][1], af[mt][2], af[mt][3],
                          aS + ((wm * 64 + mt * 16) * KP + c * 16) * 2 + offA);
                }
                uint32_t bf[4][2];
                #pragma unroll
                for (int jp = 0; jp < 2; jp++) {
                    ldsm4(bf[2 * jp][0], bf[2 * jp][1],
                          bf[2 * jp + 1][0], bf[2 * jp + 1][1],
                          bS + ((wn * 32 + jp * 16) * KP + c * 16) * 2 + offB);
                }
                #pragma unroll
                for (int mt = 0; mt < 4; mt++)
                    #pragma unroll
                    for (int nt = 0; nt < 4; nt++)
                        mma16816(acc[mt][nt], af[mt], bf[nt][0], bf[nt][1]);
            }
        }
    }

    const int which = n0 >> 10;
    const int bq = m0 >> 11;
    const int t0 = m0 & (T_DIM - 1);
    const int h  = (((n0 & 1023) + wn * 32) >> 6);

    if (which < 2) {
        __half* dst = (which == 0) ? g_qh : g_kh;
        const size_t rowbase = (size_t)(bq * H_DIM + h) * T_DIM;
        #pragma unroll
        for (int nt = 0; nt < 4; nt++) {
            const int ncol = wn * 32 + nt * 8 + 2 * (lane & 3);
            const float2 bias = *(const float2*)(b + n0 + ncol);
            const int d = ncol & 63;
            #pragma unroll
            for (int mt = 0; mt < 4; mt++) {
                const int t = t0 + wm * 64 + mt * 16 + (lane >> 2);
                *(uint32_t*)(dst + (rowbase + t) * HD + d) =
                    packh2(acc[mt][nt][0] + bias.x, acc[mt][nt][1] + bias.y);
                *(uint32_t*)(dst + (rowbase + t + 8) * HD + d) =
                    packh2(acc[mt][nt][2] + bias.x, acc[mt][nt][3] + bias.y);
            }
        }
    } else {
        // V: transposed scatter to [B,H,D,T] halves
        const size_t hb = (size_t)(bq * H_DIM + h) * HD;
        #pragma unroll
        for (int nt = 0; nt < 4; nt++) {
            const int ncol = wn * 32 + nt * 8 + 2 * (lane & 3);
            const float2 bias = *(const float2*)(b + n0 + ncol);
            const int d = ncol & 63;
            __half* r0 = g_vh + (hb + d)     * T_DIM;
            __half* r1 = g_vh + (hb + d + 1) * T_DIM;
            #pragma unroll
            for (int mt = 0; mt < 4; mt++) {
                const int t = t0 + wm * 64 + mt * 16 + (lane >> 2);
                r0[t]     = __float2half_rn(acc[mt][nt][0] + bias.x);
                r1[t]     = __float2half_rn(acc[mt][nt][1] + bias.y);
                r0[t + 8] = __float2half_rn(acc[mt][nt][2] + bias.x);
                r1[t + 8] = __float2half_rn(acc[mt][nt][3] + bias.y);
            }
        }
    }
}

// ---------------------------------------------------------------------------
// Flash attention (f16 mma): 128 q-rows/CTA, 4 warps x 32 rows. KV tiles 64,
// 4-stage cp.async ring processed in PAIRS. P feeds PV mma directly from
// softmax registers via cvt.f16x2 (no permutation, no smem round-trip).
// Rows = 64 halves padded to 72 (144B stride, 16B-aligned, conflict-free).
// ---------------------------------------------------------------------------
#define KP2 72
#define KV_B (64 * KP2 * 2)                  // 9216 bytes per tile
#define ATTN_SMEM_BYTES (8 * KV_B)           // K[4] + V[4] = 73728 B
#define SC 0.1803368801111204f   // (1/8) * log2(e)

__global__ __launch_bounds__(128, 2) void attn_f16(float* __restrict__ out)
{
    extern __shared__ char sm[];
    const uint32_t ksBase = smem_u32(sm);
    const uint32_t vtBase = ksBase + 4 * KV_B;

    const int tid  = threadIdx.x;
    const int lane = tid & 31;
    const int warp = tid >> 5;
    const int qt = (gridDim.x - 1) - blockIdx.x;   // heavy tiles first
    const int bh = blockIdx.y;

    const uint32_t offA = ((((lane & 7) + ((lane >> 3) & 1) * 8) * KP2)
                           + (lane >> 4) * 8) * 2;
    const uint32_t offB = ((((lane & 7) + (lane >> 4) * 8) * KP2)
                           + ((lane >> 3) & 1) * 8) * 2;

    const __half* Qg  = g_qh + (size_t)bh * T_DIM * HD;
    const __half* Kg  = g_kh + (size_t)bh * T_DIM * HD;
    const __half* Vgt = g_vh + (size_t)bh * HD * T_DIM;

    const int srow = tid >> 1;           // 0..63
    const int ch   = (tid & 1) * 32;     // halves: 0 or 32
    const uint32_t kDst = ksBase + (srow * KP2 + ch) * 2;
    const uint32_t vDst = vtBase + (srow * KP2 + ch) * 2;

    // ---- stage Q (raw halves) through the first K stages, pull qa ----
    {
        const uint4* qp = (const uint4*)(Qg + (size_t)(qt * 128 + tid) * HD);
        uint32_t qrow = ksBase + (tid * KP2) * 2;
        #pragma unroll
        for (int i = 0; i < 8; i++) {
            uint4 v = qp[i];
            asm volatile("st.shared.v4.b32 [%0], {%1,%2,%3,%4};"
                         :: "r"(qrow + i * 16), "r"(v.x), "r"(v.y),
                            "r"(v.z), "r"(v.w) : "memory");
        }
    }
    __syncthreads();
    uint32_t qa[2][4][4];
    #pragma unroll
    for (int mt = 0; mt < 2; mt++)
        #pragma unroll
        for (int c = 0; c < 4; c++)
            ldsm4(qa[mt][c][0], qa[mt][c][1], qa[mt][c][2], qa[mt][c][3],
                  ksBase + ((warp * 32 + mt * 16) * KP2 + c * 16) * 2 + offA);
    __syncthreads();   // qa read before K stages are reused

    // ---- prologue: KV pair 0 (tiles 0,1) in flight ----
    #pragma unroll
    for (int t = 0; t < 2; t++) {
        const uint32_t so = (uint32_t)t * KV_B;
        const __half* kp = Kg  + (size_t)(t * 64 + srow) * HD + ch;
        const __half* vp = Vgt + (size_t)srow * T_DIM + t * 64 + ch;
        #pragma unroll
        for (int i = 0; i < 4; i++) {
            cp16(kDst + so + i * 16, kp + i * 8);
            cp16(vDst + so + i * 16, vp + i * 8);
        }
    }
    CP_COMMIT();

    float oa[2][8][4] = {};
    float mr[2][2] = {{-1e30f, -1e30f}, {-1e30f, -1e30f}};
    float lv[2][2] = {};
    const int rbase = qt * 128 + warp * 32;
    const int NKV = 2 * qt + 2;              // always even

    #pragma unroll 1
    for (int p = 0; p < NKV / 2; p++) {
        CP_WAIT0();
        __syncthreads();

        if (2 * p + 2 < NKV) {
            #pragma unroll
            for (int t = 0; t < 2; t++) {
                const int kn = 2 * p + 2 + t;
                const uint32_t so = (uint32_t)(kn & 3) * KV_B;
                const __half* kp = Kg  + (size_t)(kn * 64 + srow) * HD + ch;
                const __half* vp = Vgt + (size_t)srow * T_DIM + kn * 64 + ch;
                #pragma unroll
                for (int i = 0; i < 4; i++) {
                    cp16(kDst + so + i * 16, kp + i * 8);
                    cp16(vDst + so + i * 16, vp + i * 8);
                }
            }
        }
        CP_COMMIT();

        #pragma unroll 1
        for (int tt = 0; tt < 2; tt++) {
            const int kt = 2 * p + tt;
            if (kt * 64 > rbase + 31) continue;   // fully masked for warp

            const uint32_t kB = ksBase + (uint32_t)(kt & 3) * KV_B;
            const uint32_t vB = vtBase + (uint32_t)(kt & 3) * KV_B;

            // ---- S = Q @ K^T ----
            float s[2][8][4] = {};
            #pragma unroll
            for (int c = 0; c < 4; c++) {
                #pragma unroll
                for (int jp = 0; jp < 4; jp++) {
                    uint32_t b0, b1, b2, b3;
                    ldsm4(b0, b1, b2, b3,
                          kB + ((jp * 16) * KP2 + c * 16) * 2 + offB);
                    mma16816(s[0][2 * jp],     qa[0][c], b0, b1);
                    mma16816(s[0][2 * jp + 1], qa[0][c], b2, b3);
                    mma16816(s[1][2 * jp],     qa[1][c], b0, b1);
                    mma16816(s[1][2 * jp + 1], qa[1][c], b2, b3);
                }
            }

            // ---- causal mask ----
            if (kt * 64 + 63 > rbase) {
                #pragma unroll
                for (int mt = 0; mt < 2; mt++) {
                    const int gr0 = rbase + mt * 16 + (lane >> 2);
                    const int gr1 = gr0 + 8;
                    #pragma unroll
                    for (int j = 0; j < 8; j++) {
                        const int c0 = kt * 64 + j * 8 + 2 * (lane & 3);
                        if (c0     > gr0) s[mt][j][0] = -1e30f;
                        if (c0 + 1 > gr0) s[mt][j][1] = -1e30f;
                        if (c0     > gr1) s[mt][j][2] = -1e30f;
                        if (c0 + 1 > gr1) s[mt][j][3] = -1e30f;
                    }
                }
            }

            // ---- online softmax (base-2, scale folded into ex2) ----
            #pragma unroll
            for (int mt = 0; mt < 2; mt++) {
                float mx0 = -1e30f, mx1 = -1e30f;
                #pragma unroll
                for (int j = 0; j < 8; j++) {
                    mx0 = fmaxf(mx0, fmaxf(s[mt][j][0], s[mt][j][1]));
                    mx1 = fmaxf(mx1, fmaxf(s[mt][j][2], s[mt][j][3]));
                }
                mx0 = fmaxf(mx0, __shfl_xor_sync(0xffffffff, mx0, 1));
                mx0 = fmaxf(mx0, __shfl_xor_sync(0xffffffff, mx0, 2));
                mx1 = fmaxf(mx1, __shfl_xor_sync(0xffffffff, mx1, 1));
                mx1 = fmaxf(mx1, __shfl_xor_sync(0xffffffff, mx1, 2));

                const float nm0 = fmaxf(mr[mt][0], mx0);
                const float nm1 = fmaxf(mr[mt][1], mx1);
                const float nm0c = nm0 * SC;
                const float nm1c = nm1 * SC;
                const float corr0 = ex2(fmaf(mr[mt][0], SC, -nm0c));
                const float corr1 = ex2(fmaf(mr[mt][1], SC, -nm1c));
                mr[mt][0] = nm0; mr[mt][1] = nm1;

                float sum0 = 0.0f, sum1 = 0.0f;
                #pragma unroll
                for (int j = 0; j < 8; j++) {
                    s[mt][j][0] = ex2(fmaf(s[mt][j][0], SC, -nm0c)); sum0 += s[mt][j][0];
                    s[mt][j][1] = ex2(fmaf(s[mt][j][1], SC, -nm0c)); sum0 += s[mt][j][1];
                    s[mt][j][2] = ex2(fmaf(s[mt][j][2], SC, -nm1c)); sum1 += s[mt][j][2];
                    s[mt][j][3] = ex2(fmaf(s[mt][j][3], SC, -nm1c)); sum1 += s[mt][j][3];
                }
                sum0 += __shfl_xor_sync(0xffffffff, sum0, 1);
                sum0 += __shfl_xor_sync(0xffffffff, sum0, 2);
                sum1 += __shfl_xor_sync(0xffffffff, sum1, 1);
                sum1 += __shfl_xor_sync(0xffffffff, sum1, 2);
                lv[mt][0] = lv[mt][0] * corr0 + sum0;
                lv[mt][1] = lv[mt][1] * corr1 + sum1;

                #pragma unroll
                for (int j = 0; j < 8; j++) {
                    oa[mt][j][0] *= corr0; oa[mt][j][1] *= corr0;
                    oa[mt][j][2] *= corr1; oa[mt][j][3] *= corr1;
                }
            }

            // ---- O += P @ V : A-frags packed straight from s registers ----
            #pragma unroll
            for (int kk = 0; kk < 4; kk++) {      // k16 chunk over tokens
                uint32_t A[2][4];
                #pragma unroll
                for (int mt = 0; mt < 2; mt++) {
                    A[mt][0] = packh2(s[mt][2 * kk][0],     s[mt][2 * kk][1]);
                    A[mt][1] = packh2(s[mt][2 * kk][2],     s[mt][2 * kk][3]);
                    A[mt][2] = packh2(s[mt][2 * kk + 1][0], s[mt][2 * kk + 1][1]);
                    A[mt][3] = packh2(s[mt][2 * kk + 1][2], s[mt][2 * kk + 1][3]);
                }
                #pragma unroll
                for (int jp = 0; jp < 4; jp++) {
                    uint32_t b0, b1, b2, b3;
                    ldsm4(b0, b1, b2, b3,
                          vB + ((jp * 16) * KP2 + kk * 16) * 2 + offB);
                    mma16816(oa[0][2 * jp],     A[0], b0, b1);
                    mma16816(oa[0][2 * jp + 1], A[0], b2, b3);
                    mma16816(oa[1][2 * jp],     A[1], b0, b1);
                    mma16816(oa[1][2 * jp + 1], A[1], b2, b3);
                }
            }
        }
    }

    // ---- epilogue: normalize, write [B,T,C] fp32 ----
    const int bq = bh >> 4;
    const int h  = bh & 15;
    #pragma unroll
    for (int mt = 0; mt < 2; mt++) {
        const float inv0 = 1.0f / lv[mt][0];
        const float inv1 = 1.0f / lv[mt][1];
        const int trow = rbase + mt * 16 + (lane >> 2);
        #pragma unroll
        for (int j = 0; j < 8; j++) {
            const int d = j * 8 + 2 * (lane & 3);
            float2 v0 = { oa[mt][j][0] * inv0, oa[mt][j][1] * inv0 };
            float2 v1 = { oa[mt][j][2] * inv1, oa[mt][j][3] * inv1 };
            *(float2*)(out + (size_t)(bq * T_DIM + trow) * C_DIM + h * HD + d)     = v0;
            *(float2*)(out + (size_t)(bq * T_DIM + trow + 8) * C_DIM + h * HD + d) = v1;
        }
    }
}

// ---------------------------------------------------------------------------
extern "C" void kernel_launch(void* const* d_in, const int* in_sizes, int n_in,
                              void* d_out, int out_size)
{
    const float* x = (const float*)d_in[0];   // [4, 2048, 1024]
    const float* W = (const float*)d_in[1];   // [3072, 1024]
    const float* b = (const float*)d_in[2];   // [3072]
    float* out = (float*)d_out;               // [4, 2048, 1024]

    cudaFuncSetAttribute(qkv_gemm_f16, cudaFuncAttributeMaxDynamicSharedMemorySize,
                         GEMM_SMEM_BYTES);
    cudaFuncSetAttribute(attn_f16, cudaFuncAttributeMaxDynamicSharedMemorySize,
                         ATTN_SMEM_BYTES);

    const size_t ncvt = ((size_t)M_TOT * C_DIM + (size_t)N_TOT * C_DIM) / 8;
    cvt_pre<<<(unsigned)((ncvt + 255) / 256), 256>>>(x, W);
    qkv_gemm_f16<<<dim3(N_TOT / 128, M_TOT / 128), 256, GEMM_SMEM_BYTES>>>(b);
    attn_f16<<<dim3(T_DIM / 128, B_DIM * H_DIM), 128, ATTN_SMEM_BYTES>>>(out);
}